// round 4
// baseline (speedup 1.0000x reference)
#include <cuda_runtime.h>
#include <cstdint>
#include <cstddef>

#define BATCH 64
#define INF   1024
#define OUTF  1024
#define NEXP  8
#define HID   8

// c_t[e][b] = sum_f att[b,f] * align_conv[f,e]
__device__ float g_c[NEXP * BATCH];

// ---------------------------------------------------------------------------
// packed fp32x2 helpers (FFMA2 is PTX-only on sm_103a)
// ---------------------------------------------------------------------------
__device__ __forceinline__ unsigned long long f32x2_dup(float a) {
    unsigned long long r;
    asm("mov.b64 %0, {%1, %1};" : "=l"(r) : "f"(a));
    return r;
}
__device__ __forceinline__ unsigned long long ffma2(unsigned long long a,
                                                    unsigned long long b,
                                                    unsigned long long c) {
    unsigned long long d;
    asm("fma.rn.f32x2 %0, %1, %2, %3;" : "=l"(d) : "l"(a), "l"(b), "l"(c));
    return d;
}
__device__ __forceinline__ float2 f32x2_unpack(unsigned long long v) {
    float2 r;
    asm("mov.b64 {%0, %1}, %2;" : "=f"(r.x), "=f"(r.y) : "l"(v));
    return r;
}

// ---------------------------------------------------------------------------
// Gating: one block per batch sample. pooled-mean -> tanh RNN step -> relu ->
// linear -> softmax -> fold align_conv:  c[b,e] = sum_f att[b,f]*align[f,e]
// ---------------------------------------------------------------------------
__global__ void gate_kernel(const float* __restrict__ x,
                            const float* __restrict__ align_conv,
                            const float* __restrict__ W_ih,
                            const float* __restrict__ b_ih,
                            const float* __restrict__ b_hh,
                            const float* __restrict__ W_att,
                            const float* __restrict__ b_att)
{
    const int b   = blockIdx.x;
    const int tid = threadIdx.x;
    __shared__ float red[8];

    const float* xr = x + (size_t)b * INF;
    float s = 0.f;
#pragma unroll
    for (int i = 0; i < INF / 256; i++) s += xr[tid + i * 256];
#pragma unroll
    for (int o = 16; o > 0; o >>= 1) s += __shfl_xor_sync(0xffffffffu, s, o);
    if ((tid & 31) == 0) red[tid >> 5] = s;
    __syncthreads();

    if (tid == 0) {
        float tot = 0.f;
#pragma unroll
        for (int wdx = 0; wdx < 8; wdx++) tot += red[wdx];
        const float pooled = tot * (1.0f / INF);

        float r[HID];
#pragma unroll
        for (int j = 0; j < HID; j++)
            r[j] = fmaxf(tanhf(pooled * W_ih[j] + b_ih[j] + b_hh[j]), 0.f);

        float lg[NEXP];
        float mx = -1e30f;
#pragma unroll
        for (int e = 0; e < NEXP; e++) {
            float v = b_att[e];
#pragma unroll
            for (int j = 0; j < HID; j++) v += r[j] * W_att[e * HID + j];
            lg[e] = v;
            mx = fmaxf(mx, v);
        }
        float sum = 0.f;
#pragma unroll
        for (int e = 0; e < NEXP; e++) { lg[e] = expf(lg[e] - mx); sum += lg[e]; }
        const float inv = 1.f / sum;

#pragma unroll
        for (int e2 = 0; e2 < NEXP; e2++) {
            float c = 0.f;
#pragma unroll
            for (int f = 0; f < NEXP; f++) c += (lg[f] * inv) * align_conv[f * NEXP + e2];
            g_c[e2 * BATCH + b] = c;
        }
    }
}

// ---------------------------------------------------------------------------
// GEMM: y[b,o] += sum_k (c[b,e]*x[b,i]) * w[e,o,i]  over this CTA's K chunk.
//   CTA tile: M=64 (all batches) x N=128, K=512.
//   grid = (OUTF/128 = 8, 16 k-splits); k-split z: e = z>>1, i0 = (z&1)*512.
//   256 threads: tmid = tid&7 (m), tnid = tid>>3 (n). Micro-tile 8m x 4n.
//   m set per thread: {4*tmid+mi} U {32+4*tmid+mi}  (keeps LDS.128 conflict-free)
//   fp32x2 packs adjacent n outputs; B pairs come straight from n-contiguous SMEM.
// ---------------------------------------------------------------------------
#define NTILE 128
#define KB    16
#define KCTA  512
#define NSTG  (KCTA / KB)
#define AS_S  68
#define BS_S  132

__global__ void __launch_bounds__(256) gemm_kernel(const float* __restrict__ x,
                                                   const float* __restrict__ w,
                                                   float* __restrict__ y)
{
    __shared__ __align__(16) float As[2][KB][AS_S];   // [k][m], scaled by c[m,e]
    __shared__ __align__(16) float Bs[2][KB][BS_S];   // [k][n]

    const int tid  = threadIdx.x;
    const int tmid = tid & 7;
    const int tnid = tid >> 3;
    const int nt0  = blockIdx.x * NTILE;
    const int kz   = blockIdx.y;
    const int e    = kz >> 1;
    const int i0   = (kz & 1) * KCTA;

    const float* xb = x + i0;
    const float* wb = w + ((size_t)e << 20) + (size_t)nt0 * INF + i0;

    // loader indices: 1 float4 of A + 2 float4 of B per thread per stage
    const int am  = tid >> 2;   // 0..63 : A row (batch) and B row (n, n+64)
    const int akq = tid & 3;    // float4 slot along k
    const float cs = g_c[e * BATCH + am];

    unsigned long long acc[8][2];
#pragma unroll
    for (int i = 0; i < 8; i++) { acc[i][0] = 0ull; acc[i][1] = 0ull; }

    float4 aV, bV0, bV1;

    // prologue: load + store stage 0
    aV  = *(const float4*)(xb + (size_t)am * INF + akq * 4);
    bV0 = *(const float4*)(wb + (size_t)am * INF + akq * 4);
    bV1 = *(const float4*)(wb + (size_t)(am + 64) * INF + akq * 4);
    {
        const int k4 = akq * 4;
        As[0][k4 + 0][am] = aV.x * cs;
        As[0][k4 + 1][am] = aV.y * cs;
        As[0][k4 + 2][am] = aV.z * cs;
        As[0][k4 + 3][am] = aV.w * cs;
        Bs[0][k4 + 0][am] = bV0.x;
        Bs[0][k4 + 1][am] = bV0.y;
        Bs[0][k4 + 2][am] = bV0.z;
        Bs[0][k4 + 3][am] = bV0.w;
        Bs[0][k4 + 0][am + 64] = bV1.x;
        Bs[0][k4 + 1][am + 64] = bV1.y;
        Bs[0][k4 + 2][am + 64] = bV1.z;
        Bs[0][k4 + 3][am + 64] = bV1.w;
    }
    __syncthreads();

    for (int kb = 0; kb < NSTG; kb++) {
        const int cur = kb & 1;

        if (kb + 1 < NSTG) {
            const int koff = (kb + 1) * KB + akq * 4;
            aV  = *(const float4*)(xb + (size_t)am * INF + koff);
            bV0 = *(const float4*)(wb + (size_t)am * INF + koff);
            bV1 = *(const float4*)(wb + (size_t)(am + 64) * INF + koff);
        }

#pragma unroll
        for (int kk = 0; kk < KB; kk++) {
            const float4 a1 = *(const float4*)&As[cur][kk][4 * tmid];
            const float4 a2 = *(const float4*)&As[cur][kk][32 + 4 * tmid];
            const unsigned long long b0 = *(const unsigned long long*)&Bs[cur][kk][4 * tnid];
            const unsigned long long b1 = *(const unsigned long long*)&Bs[cur][kk][4 * tnid + 2];

            unsigned long long ap0 = f32x2_dup(a1.x);
            unsigned long long ap1 = f32x2_dup(a1.y);
            unsigned long long ap2 = f32x2_dup(a1.z);
            unsigned long long ap3 = f32x2_dup(a1.w);
            unsigned long long ap4 = f32x2_dup(a2.x);
            unsigned long long ap5 = f32x2_dup(a2.y);
            unsigned long long ap6 = f32x2_dup(a2.z);
            unsigned long long ap7 = f32x2_dup(a2.w);

            acc[0][0] = ffma2(ap0, b0, acc[0][0]);  acc[0][1] = ffma2(ap0, b1, acc[0][1]);
            acc[1][0] = ffma2(ap1, b0, acc[1][0]);  acc[1][1] = ffma2(ap1, b1, acc[1][1]);
            acc[2][0] = ffma2(ap2, b0, acc[2][0]);  acc[2][1] = ffma2(ap2, b1, acc[2][1]);
            acc[3][0] = ffma2(ap3, b0, acc[3][0]);  acc[3][1] = ffma2(ap3, b1, acc[3][1]);
            acc[4][0] = ffma2(ap4, b0, acc[4][0]);  acc[4][1] = ffma2(ap4, b1, acc[4][1]);
            acc[5][0] = ffma2(ap5, b0, acc[5][0]);  acc[5][1] = ffma2(ap5, b1, acc[5][1]);
            acc[6][0] = ffma2(ap6, b0, acc[6][0]);  acc[6][1] = ffma2(ap6, b1, acc[6][1]);
            acc[7][0] = ffma2(ap7, b0, acc[7][0]);  acc[7][1] = ffma2(ap7, b1, acc[7][1]);
        }

        if (kb + 1 < NSTG) {
            const int nb = cur ^ 1;
            const int k4 = akq * 4;
            As[nb][k4 + 0][am] = aV.x * cs;
            As[nb][k4 + 1][am] = aV.y * cs;
            As[nb][k4 + 2][am] = aV.z * cs;
            As[nb][k4 + 3][am] = aV.w * cs;
            Bs[nb][k4 + 0][am] = bV0.x;
            Bs[nb][k4 + 1][am] = bV0.y;
            Bs[nb][k4 + 2][am] = bV0.z;
            Bs[nb][k4 + 3][am] = bV0.w;
            Bs[nb][k4 + 0][am + 64] = bV1.x;
            Bs[nb][k4 + 1][am + 64] = bV1.y;
            Bs[nb][k4 + 2][am + 64] = bV1.z;
            Bs[nb][k4 + 3][am + 64] = bV1.w;
        }
        __syncthreads();
    }

    // epilogue: unpack and atomically accumulate k-split partials
#pragma unroll
    for (int mi = 0; mi < 8; mi++) {
        const int m = (mi < 4) ? (4 * tmid + mi) : (32 + 4 * tmid + (mi - 4));
        float* yr = y + (size_t)m * OUTF + nt0 + 4 * tnid;
        const float2 v0 = f32x2_unpack(acc[mi][0]);
        const float2 v1 = f32x2_unpack(acc[mi][1]);
        atomicAdd(yr + 0, v0.x);
        atomicAdd(yr + 1, v0.y);
        atomicAdd(yr + 2, v1.x);
        atomicAdd(yr + 3, v1.y);
    }
}

// ---------------------------------------------------------------------------
extern "C" void kernel_launch(void* const* d_in, const int* in_sizes, int n_in,
                              void* d_out, int out_size)
{
    (void)in_sizes; (void)n_in; (void)out_size;
    const float* x          = (const float*)d_in[0];
    const float* weight     = (const float*)d_in[1];
    const float* align_conv = (const float*)d_in[2];
    const float* W_ih       = (const float*)d_in[3];
    // d_in[4] = W_hh : unused (h0 == 0)
    const float* b_ih       = (const float*)d_in[5];
    const float* b_hh       = (const float*)d_in[6];
    const float* W_att      = (const float*)d_in[7];
    const float* b_att      = (const float*)d_in[8];
    float* y = (float*)d_out;

    gate_kernel<<<BATCH, 256>>>(x, align_conv, W_ih, b_ih, b_hh, W_att, b_att);
    cudaMemsetAsync(y, 0, (size_t)BATCH * OUTF * sizeof(float));
    dim3 grid(OUTF / NTILE, 16);
    gemm_kernel<<<grid, 256>>>(x, weight, y);
}